// round 6
// baseline (speedup 1.0000x reference)
#include <cuda_runtime.h>

#define TT 100
#define BB 32768

// ---- frozen arithmetic (R5, passing): NEON 4-lane dot ----
// lanes l0..l3 strided, pairwise reduce (l0+l1)+(l2+l3), scalar fma tail.

__device__ __forceinline__ float reduce4(float l0, float l1, float l2, float l3) {
    return __fadd_rn(__fadd_rn(l0, l1), __fadd_rn(l2, l3));
}

__global__ __launch_bounds__(32) void snn_kernel(
    const float* __restrict__ x,
    const float* __restrict__ w_s1, const float* __restrict__ b_s1,
    const float* __restrict__ w_s2, const float* __restrict__ b_s2,
    const float* __restrict__ w_c1, const float* __restrict__ b_c1,
    const float* __restrict__ w_co, const float* __restrict__ b_co,
    const float* __restrict__ w_ro, const float* __restrict__ b_ro,
    float* __restrict__ out)
{
    // weights (rows 16B-aligned; c1/ro rows padded to 16 floats where needed)
    __shared__ float s_ws1[28 * 32];      // stride 32
    __shared__ float s_ws2[14 * 28];      // stride 28 (28%4==0, aligned)
    __shared__ float s_wc1[8 * 16];       // stride 16 (padded from 14)
    __shared__ float s_wco[3 * 8];        // stride 8
    __shared__ float s_wro[16];           // padded from 14
    __shared__ float s_bs1[28], s_bs2[14], s_bc1[8], s_bco[3], s_bro[1];
    // membrane state: [neuron][tid], conflict-free columns
    __shared__ float s_m1[28][32];
    __shared__ float s_m2[14][32];
    __shared__ float s_mc1[8][32];
    __shared__ float s_mco[3][32];
    __shared__ float s_mro[32];

    const int tid = threadIdx.x;
    for (int i = tid; i < 28 * 32; i += 32) s_ws1[i] = w_s1[i];
    for (int i = tid; i < 14 * 28; i += 32) s_ws2[i] = w_s2[i];
    for (int i = tid; i < 8 * 16;  i += 32) s_wc1[i] = (i % 16 < 14) ? w_c1[(i / 16) * 14 + (i % 16)] : 0.0f;
    for (int i = tid; i < 3 * 8;   i += 32) s_wco[i] = w_co[i];
    if (tid < 16) s_wro[tid] = (tid < 14) ? w_ro[tid] : 0.0f;
    for (int i = tid; i < 28; i += 32) s_bs1[i] = b_s1[i];
    for (int i = tid; i < 14; i += 32) s_bs2[i] = b_s2[i];
    for (int i = tid; i < 8;  i += 32) s_bc1[i] = b_c1[i];
    for (int i = tid; i < 3;  i += 32) s_bco[i] = b_co[i];
    if (tid == 0) s_bro[0] = b_ro[0];

    #pragma unroll
    for (int j = 0; j < 28; j++) s_m1[j][tid] = 0.0f;
    #pragma unroll
    for (int j = 0; j < 14; j++) s_m2[j][tid] = 0.0f;
    #pragma unroll
    for (int j = 0; j < 8; j++) s_mc1[j][tid] = 0.0f;
    #pragma unroll
    for (int j = 0; j < 3; j++) s_mco[j][tid] = 0.0f;
    s_mro[tid] = 0.0f;
    __syncthreads();

    const int b = blockIdx.x * 32 + tid;

    float* o_mco   = out;                          // (T,B,3)
    float* o_spkc1 = out + (size_t)TT * BB * 3;    // (T,B,8)
    float* o_mro   = out + (size_t)TT * BB * 11;   // (T,B,1)
    float* o_spk1  = out + (size_t)TT * BB * 12;   // (T,B,28)
    float* o_spk2  = out + (size_t)TT * BB * 40;   // (T,B,14)

    for (int t = 0; t < TT; t++) {
        const size_t base = (size_t)t * BB + b;

        // ---- load x_t[b][0:32] as 8 float4 (contiguous 128B/thread) ----
        float4 xv[8];
        const float4* xt = (const float4*)(x + base * 32);
        #pragma unroll
        for (int i = 0; i < 8; i++) xv[i] = xt[i];

        // ---- layer s1: 32 -> 28 ----
        float spk1[28];
        #pragma unroll
        for (int j = 0; j < 28; j++) {
            const float4* wr = (const float4*)&s_ws1[j * 32];
            float l0 = 0.0f, l1 = 0.0f, l2 = 0.0f, l3 = 0.0f;
            #pragma unroll
            for (int i = 0; i < 8; i++) {
                float4 w4 = wr[i];
                l0 = fmaf(w4.x, xv[i].x, l0);
                l1 = fmaf(w4.y, xv[i].y, l1);
                l2 = fmaf(w4.z, xv[i].z, l2);
                l3 = fmaf(w4.w, xv[i].w, l3);
            }
            float cur = __fadd_rn(reduce4(l0, l1, l2, l3), s_bs1[j]);
            float m   = s_m1[j][tid];
            float rst = (m > 1.0f) ? 1.0f : 0.0f;       // reset uses PREVIOUS mem
            float nm  = __fadd_rn(fmaf(0.9f, m, cur), -rst);
            s_m1[j][tid] = nm;
            spk1[j] = (nm > 1.0f) ? 1.0f : 0.0f;
        }

        // ---- layer s2: 28 -> 14 ----
        float spk2[14];
        #pragma unroll
        for (int j = 0; j < 14; j++) {
            const float4* wr = (const float4*)&s_ws2[j * 28];
            const float4* vr = (const float4*)spk1;
            float l0 = 0.0f, l1 = 0.0f, l2 = 0.0f, l3 = 0.0f;
            #pragma unroll
            for (int i = 0; i < 7; i++) {
                float4 w4 = wr[i];
                float4 v4 = vr[i];
                l0 = fmaf(w4.x, v4.x, l0);
                l1 = fmaf(w4.y, v4.y, l1);
                l2 = fmaf(w4.z, v4.z, l2);
                l3 = fmaf(w4.w, v4.w, l3);
            }
            float cur = __fadd_rn(reduce4(l0, l1, l2, l3), s_bs2[j]);
            float m   = s_m2[j][tid];
            float rst = (m > 1.0f) ? 1.0f : 0.0f;
            float nm  = __fadd_rn(fmaf(0.9f, m, cur), -rst);
            s_m2[j][tid] = nm;
            spk2[j] = (nm > 1.0f) ? 1.0f : 0.0f;
        }

        // ---- layer c1: 14 -> 8 (rows padded to 16; K=14: 3 vec iters + tail 12,13) ----
        float spkc1[8];
        #pragma unroll
        for (int j = 0; j < 8; j++) {
            const float4* wr = (const float4*)&s_wc1[j * 16];
            const float4* vr = (const float4*)spk2;
            float l0 = 0.0f, l1 = 0.0f, l2 = 0.0f, l3 = 0.0f;
            #pragma unroll
            for (int i = 0; i < 3; i++) {
                float4 w4 = wr[i];
                float4 v4 = vr[i];
                l0 = fmaf(w4.x, v4.x, l0);
                l1 = fmaf(w4.y, v4.y, l1);
                l2 = fmaf(w4.z, v4.z, l2);
                l3 = fmaf(w4.w, v4.w, l3);
            }
            float s = reduce4(l0, l1, l2, l3);
            s = fmaf(s_wc1[j * 16 + 12], spk2[12], s);
            s = fmaf(s_wc1[j * 16 + 13], spk2[13], s);
            float cur = __fadd_rn(s, s_bc1[j]);
            float m   = s_mc1[j][tid];
            float rst = (m > 1.0f) ? 1.0f : 0.0f;
            float nm  = __fadd_rn(fmaf(0.9f, m, cur), -rst);
            s_mc1[j][tid] = nm;
            spkc1[j] = (nm > 1.0f) ? 1.0f : 0.0f;
        }

        // ---- layer co: 8 -> 3 (only mem recorded) ----
        float mco_v[3];
        #pragma unroll
        for (int j = 0; j < 3; j++) {
            const float4* wr = (const float4*)&s_wco[j * 8];
            const float4* vr = (const float4*)spkc1;
            float l0 = 0.0f, l1 = 0.0f, l2 = 0.0f, l3 = 0.0f;
            #pragma unroll
            for (int i = 0; i < 2; i++) {
                float4 w4 = wr[i];
                float4 v4 = vr[i];
                l0 = fmaf(w4.x, v4.x, l0);
                l1 = fmaf(w4.y, v4.y, l1);
                l2 = fmaf(w4.z, v4.z, l2);
                l3 = fmaf(w4.w, v4.w, l3);
            }
            float cur = __fadd_rn(reduce4(l0, l1, l2, l3), s_bco[j]);
            float m   = s_mco[j][tid];
            float rst = (m > 1.0f) ? 1.0f : 0.0f;
            float nm  = __fadd_rn(fmaf(0.9f, m, cur), -rst);
            s_mco[j][tid] = nm;
            mco_v[j] = nm;
        }

        // ---- layer ro: 14 -> 1 (only mem recorded) ----
        float mro_v;
        {
            const float4* wr = (const float4*)s_wro;
            const float4* vr = (const float4*)spk2;
            float l0 = 0.0f, l1 = 0.0f, l2 = 0.0f, l3 = 0.0f;
            #pragma unroll
            for (int i = 0; i < 3; i++) {
                float4 w4 = wr[i];
                float4 v4 = vr[i];
                l0 = fmaf(w4.x, v4.x, l0);
                l1 = fmaf(w4.y, v4.y, l1);
                l2 = fmaf(w4.z, v4.z, l2);
                l3 = fmaf(w4.w, v4.w, l3);
            }
            float s = reduce4(l0, l1, l2, l3);
            s = fmaf(s_wro[12], spk2[12], s);
            s = fmaf(s_wro[13], spk2[13], s);
            float cur = __fadd_rn(s, s_bro[0]);
            float m   = s_mro[tid];
            float rst = (m > 1.0f) ? 1.0f : 0.0f;
            float nm  = __fadd_rn(fmaf(0.9f, m, cur), -rst);
            s_mro[tid] = nm;
            mro_v = nm;
        }

        // ---- stores (vectorized, coalesced) ----
        {
            float* p = o_mco + base * 3;
            p[0] = mco_v[0]; p[1] = mco_v[1]; p[2] = mco_v[2];
        }
        {
            float4* q = (float4*)(o_spkc1 + base * 8);
            q[0] = make_float4(spkc1[0], spkc1[1], spkc1[2], spkc1[3]);
            q[1] = make_float4(spkc1[4], spkc1[5], spkc1[6], spkc1[7]);
        }
        o_mro[base] = mro_v;
        {
            float4* r = (float4*)(o_spk1 + base * 28);
            #pragma unroll
            for (int j = 0; j < 7; j++)
                r[j] = make_float4(spk1[4 * j], spk1[4 * j + 1],
                                   spk1[4 * j + 2], spk1[4 * j + 3]);
        }
        {
            float2* s2 = (float2*)(o_spk2 + base * 14);
            #pragma unroll
            for (int j = 0; j < 7; j++)
                s2[j] = make_float2(spk2[2 * j], spk2[2 * j + 1]);
        }
    }
}

extern "C" void kernel_launch(void* const* d_in, const int* in_sizes, int n_in,
                              void* d_out, int out_size) {
    snn_kernel<<<BB / 32, 32>>>(
        (const float*)d_in[0],
        (const float*)d_in[1],  (const float*)d_in[2],
        (const float*)d_in[3],  (const float*)d_in[4],
        (const float*)d_in[5],  (const float*)d_in[6],
        (const float*)d_in[7],  (const float*)d_in[8],
        (const float*)d_in[9],  (const float*)d_in[10],
        (float*)d_out);
}

// round 7
// speedup vs baseline: 9.1544x; 9.1544x over previous
#include <cuda_runtime.h>

#define TT 100
#define BB 32768

// ---- frozen arithmetic (R5, passing): NEON 4-lane dot ----
// lanes l0..l3 strided over float4 groups, pairwise reduce (l0+l1)+(l2+l3),
// scalar fma tail; bias added after; LIF: fmaf(0.9,m,cur) - reset.

__device__ __forceinline__ float reduce4(float l0, float l1, float l2, float l3) {
    return __fadd_rn(__fadd_rn(l0, l1), __fadd_rn(l2, l3));
}

__global__ __launch_bounds__(32) void snn_kernel(
    const float* __restrict__ x,
    const float* __restrict__ w_s1, const float* __restrict__ b_s1,
    const float* __restrict__ w_s2, const float* __restrict__ b_s2,
    const float* __restrict__ w_c1, const float* __restrict__ b_c1,
    const float* __restrict__ w_co, const float* __restrict__ b_co,
    const float* __restrict__ w_ro, const float* __restrict__ b_ro,
    float* __restrict__ out)
{
    // weights, broadcast-read (rows 16B-aligned; c1/ro padded to stride 16)
    __shared__ float s_ws1[28 * 32];
    __shared__ float s_ws2[14 * 28];
    __shared__ float s_wc1[8 * 16];
    __shared__ float s_wco[3 * 8];
    __shared__ float s_wro[16];
    __shared__ float s_bs1[28], s_bs2[14], s_bc1[8], s_bco[3], s_bro[1];
    // thread-private columns (dynamic-indexable without local memory)
    __shared__ float s_m1[28][32];
    __shared__ float s_m2[14][32];
    __shared__ float s_mc1[8][32];
    __shared__ float s_spk1[28][32];
    __shared__ float s_spk2[14][32];
    __shared__ float s_spkc1[8][32];

    const int tid = threadIdx.x;
    for (int i = tid; i < 28 * 32; i += 32) s_ws1[i] = w_s1[i];
    for (int i = tid; i < 14 * 28; i += 32) s_ws2[i] = w_s2[i];
    for (int i = tid; i < 8 * 16;  i += 32) s_wc1[i] = (i % 16 < 14) ? w_c1[(i / 16) * 14 + (i % 16)] : 0.0f;
    for (int i = tid; i < 3 * 8;   i += 32) s_wco[i] = w_co[i];
    if (tid < 16) s_wro[tid] = (tid < 14) ? w_ro[tid] : 0.0f;
    for (int i = tid; i < 28; i += 32) s_bs1[i] = b_s1[i];
    for (int i = tid; i < 14; i += 32) s_bs2[i] = b_s2[i];
    for (int i = tid; i < 8;  i += 32) s_bc1[i] = b_c1[i];
    for (int i = tid; i < 3;  i += 32) s_bco[i] = b_co[i];
    if (tid == 0) s_bro[0] = b_ro[0];

    for (int j = 0; j < 28; j++) s_m1[j][tid] = 0.0f;
    for (int j = 0; j < 14; j++) s_m2[j][tid] = 0.0f;
    for (int j = 0; j < 8;  j++) s_mc1[j][tid] = 0.0f;
    float mco0 = 0.0f, mco1 = 0.0f, mco2 = 0.0f, mro = 0.0f;
    __syncthreads();

    const int b = blockIdx.x * 32 + tid;

    float* o_mco   = out;                          // (T,B,3)
    float* o_spkc1 = out + (size_t)TT * BB * 3;    // (T,B,8)
    float* o_mro   = out + (size_t)TT * BB * 11;   // (T,B,1)
    float* o_spk1  = out + (size_t)TT * BB * 12;   // (T,B,28)
    float* o_spk2  = out + (size_t)TT * BB * 40;   // (T,B,14)

    // prefetch x for t=0
    float4 xv[8];
    {
        const float4* xt = (const float4*)(x + ((size_t)0 * BB + b) * 32);
        #pragma unroll
        for (int i = 0; i < 8; i++) xv[i] = xt[i];
    }

    #pragma unroll 1
    for (int t = 0; t < TT; t++) {
        const size_t base = (size_t)t * BB + b;

        // ---- prefetch x for t+1 (clamped; overlaps this step's compute) ----
        float4 xn[8];
        {
            int tn = (t + 1 < TT) ? (t + 1) : (TT - 1);
            const float4* xt2 = (const float4*)(x + ((size_t)tn * BB + b) * 32);
            #pragma unroll
            for (int i = 0; i < 8; i++) xn[i] = xt2[i];
        }

        // ---- layer s1: 32 -> 28 ----
        #pragma unroll 4
        for (int j = 0; j < 28; j++) {
            const float4* wr = (const float4*)&s_ws1[j * 32];
            float l0 = 0.0f, l1 = 0.0f, l2 = 0.0f, l3 = 0.0f;
            #pragma unroll
            for (int i = 0; i < 8; i++) {
                float4 w4 = wr[i];
                l0 = fmaf(w4.x, xv[i].x, l0);
                l1 = fmaf(w4.y, xv[i].y, l1);
                l2 = fmaf(w4.z, xv[i].z, l2);
                l3 = fmaf(w4.w, xv[i].w, l3);
            }
            float cur = __fadd_rn(reduce4(l0, l1, l2, l3), s_bs1[j]);
            float m   = s_m1[j][tid];
            float rst = (m > 1.0f) ? 1.0f : 0.0f;      // reset uses PREVIOUS mem
            float nm  = __fadd_rn(fmaf(0.9f, m, cur), -rst);
            s_m1[j][tid]   = nm;
            s_spk1[j][tid] = (nm > 1.0f) ? 1.0f : 0.0f;
        }

        // reload spk1 into registers (constant-indexed)
        float spk1r[28];
        #pragma unroll
        for (int i = 0; i < 28; i++) spk1r[i] = s_spk1[i][tid];

        // ---- layer s2: 28 -> 14 ----
        #pragma unroll 4
        for (int j = 0; j < 14; j++) {
            const float4* wr = (const float4*)&s_ws2[j * 28];
            const float4* vr = (const float4*)spk1r;
            float l0 = 0.0f, l1 = 0.0f, l2 = 0.0f, l3 = 0.0f;
            #pragma unroll
            for (int i = 0; i < 7; i++) {
                float4 w4 = wr[i];
                float4 v4 = vr[i];
                l0 = fmaf(w4.x, v4.x, l0);
                l1 = fmaf(w4.y, v4.y, l1);
                l2 = fmaf(w4.z, v4.z, l2);
                l3 = fmaf(w4.w, v4.w, l3);
            }
            float cur = __fadd_rn(reduce4(l0, l1, l2, l3), s_bs2[j]);
            float m   = s_m2[j][tid];
            float rst = (m > 1.0f) ? 1.0f : 0.0f;
            float nm  = __fadd_rn(fmaf(0.9f, m, cur), -rst);
            s_m2[j][tid]   = nm;
            s_spk2[j][tid] = (nm > 1.0f) ? 1.0f : 0.0f;
        }

        float spk2r[14];
        #pragma unroll
        for (int i = 0; i < 14; i++) spk2r[i] = s_spk2[i][tid];

        // ---- layer c1: 14 -> 8 (3 vec groups + tail 12,13) ----
        #pragma unroll 4
        for (int j = 0; j < 8; j++) {
            const float4* wr = (const float4*)&s_wc1[j * 16];
            const float4* vr = (const float4*)spk2r;
            float l0 = 0.0f, l1 = 0.0f, l2 = 0.0f, l3 = 0.0f;
            #pragma unroll
            for (int i = 0; i < 3; i++) {
                float4 w4 = wr[i];
                float4 v4 = vr[i];
                l0 = fmaf(w4.x, v4.x, l0);
                l1 = fmaf(w4.y, v4.y, l1);
                l2 = fmaf(w4.z, v4.z, l2);
                l3 = fmaf(w4.w, v4.w, l3);
            }
            float s = reduce4(l0, l1, l2, l3);
            s = fmaf(s_wc1[j * 16 + 12], spk2r[12], s);
            s = fmaf(s_wc1[j * 16 + 13], spk2r[13], s);
            float cur = __fadd_rn(s, s_bc1[j]);
            float m   = s_mc1[j][tid];
            float rst = (m > 1.0f) ? 1.0f : 0.0f;
            float nm  = __fadd_rn(fmaf(0.9f, m, cur), -rst);
            s_mc1[j][tid]   = nm;
            s_spkc1[j][tid] = (nm > 1.0f) ? 1.0f : 0.0f;
        }

        float spkc1r[8];
        #pragma unroll
        for (int i = 0; i < 8; i++) spkc1r[i] = s_spkc1[i][tid];

        // ---- layer co: 8 -> 3 (fully unrolled; mem in regs) ----
        {
            const float4* vr = (const float4*)spkc1r;
            #pragma unroll
            for (int j = 0; j < 3; j++) {
                const float4* wr = (const float4*)&s_wco[j * 8];
                float l0 = 0.0f, l1 = 0.0f, l2 = 0.0f, l3 = 0.0f;
                #pragma unroll
                for (int i = 0; i < 2; i++) {
                    float4 w4 = wr[i];
                    float4 v4 = vr[i];
                    l0 = fmaf(w4.x, v4.x, l0);
                    l1 = fmaf(w4.y, v4.y, l1);
                    l2 = fmaf(w4.z, v4.z, l2);
                    l3 = fmaf(w4.w, v4.w, l3);
                }
                float cur = __fadd_rn(reduce4(l0, l1, l2, l3), s_bco[j]);
                float m   = (j == 0) ? mco0 : (j == 1) ? mco1 : mco2;
                float rst = (m > 1.0f) ? 1.0f : 0.0f;
                float nm  = __fadd_rn(fmaf(0.9f, m, cur), -rst);
                if (j == 0) mco0 = nm; else if (j == 1) mco1 = nm; else mco2 = nm;
            }
        }

        // ---- layer ro: 14 -> 1 (mem in reg) ----
        {
            const float4* wr = (const float4*)s_wro;
            const float4* vr = (const float4*)spk2r;
            float l0 = 0.0f, l1 = 0.0f, l2 = 0.0f, l3 = 0.0f;
            #pragma unroll
            for (int i = 0; i < 3; i++) {
                float4 w4 = wr[i];
                float4 v4 = vr[i];
                l0 = fmaf(w4.x, v4.x, l0);
                l1 = fmaf(w4.y, v4.y, l1);
                l2 = fmaf(w4.z, v4.z, l2);
                l3 = fmaf(w4.w, v4.w, l3);
            }
            float s = reduce4(l0, l1, l2, l3);
            s = fmaf(s_wro[12], spk2r[12], s);
            s = fmaf(s_wro[13], spk2r[13], s);
            float cur = __fadd_rn(s, s_bro[0]);
            float rst = (mro > 1.0f) ? 1.0f : 0.0f;
            mro = __fadd_rn(fmaf(0.9f, mro, cur), -rst);
        }

        // ---- stores (vectorized, coalesced) ----
        {
            float* p = o_mco + base * 3;
            p[0] = mco0; p[1] = mco1; p[2] = mco2;
        }
        {
            float4* q = (float4*)(o_spkc1 + base * 8);
            q[0] = make_float4(spkc1r[0], spkc1r[1], spkc1r[2], spkc1r[3]);
            q[1] = make_float4(spkc1r[4], spkc1r[5], spkc1r[6], spkc1r[7]);
        }
        o_mro[base] = mro;
        {
            float4* r = (float4*)(o_spk1 + base * 28);
            #pragma unroll
            for (int j = 0; j < 7; j++)
                r[j] = make_float4(spk1r[4 * j], spk1r[4 * j + 1],
                                   spk1r[4 * j + 2], spk1r[4 * j + 3]);
        }
        {
            float2* s2 = (float2*)(o_spk2 + base * 14);
            #pragma unroll
            for (int j = 0; j < 7; j++)
                s2[j] = make_float2(spk2r[2 * j], spk2r[2 * j + 1]);
        }

        // rotate prefetched x
        #pragma unroll
        for (int i = 0; i < 8; i++) xv[i] = xn[i];
    }
}

extern "C" void kernel_launch(void* const* d_in, const int* in_sizes, int n_in,
                              void* d_out, int out_size) {
    snn_kernel<<<BB / 32, 32>>>(
        (const float*)d_in[0],
        (const float*)d_in[1],  (const float*)d_in[2],
        (const float*)d_in[3],  (const float*)d_in[4],
        (const float*)d_in[5],  (const float*)d_in[6],
        (const float*)d_in[7],  (const float*)d_in[8],
        (const float*)d_in[9],  (const float*)d_in[10],
        (float*)d_out);
}

// round 8
// speedup vs baseline: 9.5613x; 1.0444x over previous
#include <cuda_runtime.h>

#define TT 100
#define BB 32768

// ---- frozen arithmetic (R5, passing): NEON 4-lane dot ----
// lanes l0..l3 strided over float4 groups, pairwise reduce (l0+l1)+(l2+l3),
// scalar fma tail; bias after; LIF: fmaf(0.9,m,cur) - reset.
// R8: lanes (l0,l1) and (l2,l3) packed into f32x2 — two independent
// correctly-rounded fp32 FMAs per instruction, bit-identical per lane.

typedef unsigned long long u64;

__device__ __forceinline__ u64 fma2(u64 a, u64 b, u64 c) {
    u64 d;
    asm("fma.rn.f32x2 %0, %1, %2, %3;" : "=l"(d) : "l"(a), "l"(b), "l"(c));
    return d;
}

__device__ __forceinline__ float reduce2x2(u64 a01, u64 a23) {
    float l0, l1, l2, l3;
    asm("mov.b64 {%0,%1}, %2;" : "=f"(l0), "=f"(l1) : "l"(a01));
    asm("mov.b64 {%0,%1}, %2;" : "=f"(l2), "=f"(l3) : "l"(a23));
    return __fadd_rn(__fadd_rn(l0, l1), __fadd_rn(l2, l3));
}

__global__ __launch_bounds__(32) void snn_kernel(
    const float* __restrict__ x,
    const float* __restrict__ w_s1, const float* __restrict__ b_s1,
    const float* __restrict__ w_s2, const float* __restrict__ b_s2,
    const float* __restrict__ w_c1, const float* __restrict__ b_c1,
    const float* __restrict__ w_co, const float* __restrict__ b_co,
    const float* __restrict__ w_ro, const float* __restrict__ b_ro,
    float* __restrict__ out)
{
    __shared__ float s_ws1[28 * 32];
    __shared__ float s_ws2[14 * 28];
    __shared__ float s_wc1[8 * 16];
    __shared__ float s_wco[3 * 8];
    __shared__ float s_wro[16];
    __shared__ float s_bs1[28], s_bs2[14], s_bc1[8], s_bco[3], s_bro[1];
    __shared__ float s_m1[28][32];
    __shared__ float s_m2[14][32];
    __shared__ float s_mc1[8][32];
    __shared__ float s_spk1[28][32];
    __shared__ float s_spk2[14][32];
    __shared__ float s_spkc1[8][32];

    const int tid = threadIdx.x;
    for (int i = tid; i < 28 * 32; i += 32) s_ws1[i] = w_s1[i];
    for (int i = tid; i < 14 * 28; i += 32) s_ws2[i] = w_s2[i];
    for (int i = tid; i < 8 * 16;  i += 32) s_wc1[i] = (i % 16 < 14) ? w_c1[(i / 16) * 14 + (i % 16)] : 0.0f;
    for (int i = tid; i < 3 * 8;   i += 32) s_wco[i] = w_co[i];
    if (tid < 16) s_wro[tid] = (tid < 14) ? w_ro[tid] : 0.0f;
    for (int i = tid; i < 28; i += 32) s_bs1[i] = b_s1[i];
    for (int i = tid; i < 14; i += 32) s_bs2[i] = b_s2[i];
    for (int i = tid; i < 8;  i += 32) s_bc1[i] = b_c1[i];
    for (int i = tid; i < 3;  i += 32) s_bco[i] = b_co[i];
    if (tid == 0) s_bro[0] = b_ro[0];

    for (int j = 0; j < 28; j++) s_m1[j][tid] = 0.0f;
    for (int j = 0; j < 14; j++) s_m2[j][tid] = 0.0f;
    for (int j = 0; j < 8;  j++) s_mc1[j][tid] = 0.0f;
    float mco0 = 0.0f, mco1 = 0.0f, mco2 = 0.0f, mro = 0.0f;
    __syncthreads();

    const int b = blockIdx.x * 32 + tid;

    float* o_mco   = out;                          // (T,B,3)
    float* o_spkc1 = out + (size_t)TT * BB * 3;    // (T,B,8)
    float* o_mro   = out + (size_t)TT * BB * 11;   // (T,B,1)
    float* o_spk1  = out + (size_t)TT * BB * 12;   // (T,B,28)
    float* o_spk2  = out + (size_t)TT * BB * 40;   // (T,B,14)

    // prefetch x for t=0 as packed 16B groups: .x=(f0,f1) .y=(f2,f3)
    ulonglong2 xv[8];
    {
        const ulonglong2* xt = (const ulonglong2*)(x + ((size_t)0 * BB + b) * 32);
        #pragma unroll
        for (int i = 0; i < 8; i++) xv[i] = xt[i];
    }

    #pragma unroll 1
    for (int t = 0; t < TT; t++) {
        const size_t base = (size_t)t * BB + b;

        // ---- prefetch x for t+1 (clamped; overlaps this step's compute) ----
        ulonglong2 xn[8];
        {
            int tn = (t + 1 < TT) ? (t + 1) : (TT - 1);
            const ulonglong2* xt2 = (const ulonglong2*)(x + ((size_t)tn * BB + b) * 32);
            #pragma unroll
            for (int i = 0; i < 8; i++) xn[i] = xt2[i];
        }

        // ---- layer s1: 32 -> 28 ----
        #pragma unroll 4
        for (int j = 0; j < 28; j++) {
            const ulonglong2* wr = (const ulonglong2*)&s_ws1[j * 32];
            u64 a01 = 0ull, a23 = 0ull;
            #pragma unroll
            for (int i = 0; i < 8; i++) {
                ulonglong2 w = wr[i];
                a01 = fma2(w.x, xv[i].x, a01);
                a23 = fma2(w.y, xv[i].y, a23);
            }
            float cur = __fadd_rn(reduce2x2(a01, a23), s_bs1[j]);
            float m   = s_m1[j][tid];
            float rst = (m > 1.0f) ? 1.0f : 0.0f;      // reset uses PREVIOUS mem
            float nm  = __fadd_rn(fmaf(0.9f, m, cur), -rst);
            s_m1[j][tid]   = nm;
            s_spk1[j][tid] = (nm > 1.0f) ? 1.0f : 0.0f;
        }

        // reload spk1 (constant-indexed)
        float spk1r[28];
        #pragma unroll
        for (int i = 0; i < 28; i++) spk1r[i] = s_spk1[i][tid];

        // ---- layer s2: 28 -> 14 ----
        #pragma unroll 4
        for (int j = 0; j < 14; j++) {
            const ulonglong2* wr = (const ulonglong2*)&s_ws2[j * 28];
            const ulonglong2* vr = (const ulonglong2*)spk1r;
            u64 a01 = 0ull, a23 = 0ull;
            #pragma unroll
            for (int i = 0; i < 7; i++) {
                ulonglong2 w = wr[i];
                ulonglong2 v = vr[i];
                a01 = fma2(w.x, v.x, a01);
                a23 = fma2(w.y, v.y, a23);
            }
            float cur = __fadd_rn(reduce2x2(a01, a23), s_bs2[j]);
            float m   = s_m2[j][tid];
            float rst = (m > 1.0f) ? 1.0f : 0.0f;
            float nm  = __fadd_rn(fmaf(0.9f, m, cur), -rst);
            s_m2[j][tid]   = nm;
            s_spk2[j][tid] = (nm > 1.0f) ? 1.0f : 0.0f;
        }

        float spk2r[14];
        #pragma unroll
        for (int i = 0; i < 14; i++) spk2r[i] = s_spk2[i][tid];

        // ---- layer c1: 14 -> 8 (3 vec groups + scalar tail 12,13) ----
        #pragma unroll 4
        for (int j = 0; j < 8; j++) {
            const ulonglong2* wr = (const ulonglong2*)&s_wc1[j * 16];
            const ulonglong2* vr = (const ulonglong2*)spk2r;
            u64 a01 = 0ull, a23 = 0ull;
            #pragma unroll
            for (int i = 0; i < 3; i++) {
                ulonglong2 w = wr[i];
                ulonglong2 v = vr[i];
                a01 = fma2(w.x, v.x, a01);
                a23 = fma2(w.y, v.y, a23);
            }
            float s = reduce2x2(a01, a23);
            s = fmaf(s_wc1[j * 16 + 12], spk2r[12], s);
            s = fmaf(s_wc1[j * 16 + 13], spk2r[13], s);
            float cur = __fadd_rn(s, s_bc1[j]);
            float m   = s_mc1[j][tid];
            float rst = (m > 1.0f) ? 1.0f : 0.0f;
            float nm  = __fadd_rn(fmaf(0.9f, m, cur), -rst);
            s_mc1[j][tid]   = nm;
            s_spkc1[j][tid] = (nm > 1.0f) ? 1.0f : 0.0f;
        }

        float spkc1r[8];
        #pragma unroll
        for (int i = 0; i < 8; i++) spkc1r[i] = s_spkc1[i][tid];

        // ---- layer co: 8 -> 3 (mem in regs) ----
        {
            const ulonglong2* vr = (const ulonglong2*)spkc1r;
            #pragma unroll
            for (int j = 0; j < 3; j++) {
                const ulonglong2* wr = (const ulonglong2*)&s_wco[j * 8];
                u64 a01 = 0ull, a23 = 0ull;
                #pragma unroll
                for (int i = 0; i < 2; i++) {
                    ulonglong2 w = wr[i];
                    ulonglong2 v = vr[i];
                    a01 = fma2(w.x, v.x, a01);
                    a23 = fma2(w.y, v.y, a23);
                }
                float cur = __fadd_rn(reduce2x2(a01, a23), s_bco[j]);
                float m   = (j == 0) ? mco0 : (j == 1) ? mco1 : mco2;
                float rst = (m > 1.0f) ? 1.0f : 0.0f;
                float nm  = __fadd_rn(fmaf(0.9f, m, cur), -rst);
                if (j == 0) mco0 = nm; else if (j == 1) mco1 = nm; else mco2 = nm;
            }
        }

        // ---- layer ro: 14 -> 1 (mem in reg) ----
        {
            const ulonglong2* wr = (const ulonglong2*)s_wro;
            const ulonglong2* vr = (const ulonglong2*)spk2r;
            u64 a01 = 0ull, a23 = 0ull;
            #pragma unroll
            for (int i = 0; i < 3; i++) {
                ulonglong2 w = wr[i];
                ulonglong2 v = vr[i];
                a01 = fma2(w.x, v.x, a01);
                a23 = fma2(w.y, v.y, a23);
            }
            float s = reduce2x2(a01, a23);
            s = fmaf(s_wro[12], spk2r[12], s);
            s = fmaf(s_wro[13], spk2r[13], s);
            float cur = __fadd_rn(s, s_bro[0]);
            float rst = (mro > 1.0f) ? 1.0f : 0.0f;
            mro = __fadd_rn(fmaf(0.9f, mro, cur), -rst);
        }

        // ---- stores (vectorized, coalesced) ----
        {
            float* p = o_mco + base * 3;
            p[0] = mco0; p[1] = mco1; p[2] = mco2;
        }
        {
            float4* q = (float4*)(o_spkc1 + base * 8);
            q[0] = make_float4(spkc1r[0], spkc1r[1], spkc1r[2], spkc1r[3]);
            q[1] = make_float4(spkc1r[4], spkc1r[5], spkc1r[6], spkc1r[7]);
        }
        o_mro[base] = mro;
        {
            float4* r = (float4*)(o_spk1 + base * 28);
            #pragma unroll
            for (int j = 0; j < 7; j++)
                r[j] = make_float4(spk1r[4 * j], spk1r[4 * j + 1],
                                   spk1r[4 * j + 2], spk1r[4 * j + 3]);
        }
        {
            float2* s2 = (float2*)(o_spk2 + base * 14);
            #pragma unroll
            for (int j = 0; j < 7; j++)
                s2[j] = make_float2(spk2r[2 * j], spk2r[2 * j + 1]);
        }

        // rotate prefetched x
        #pragma unroll
        for (int i = 0; i < 8; i++) xv[i] = xn[i];
    }
}

extern "C" void kernel_launch(void* const* d_in, const int* in_sizes, int n_in,
                              void* d_out, int out_size) {
    snn_kernel<<<BB / 32, 32>>>(
        (const float*)d_in[0],
        (const float*)d_in[1],  (const float*)d_in[2],
        (const float*)d_in[3],  (const float*)d_in[4],
        (const float*)d_in[5],  (const float*)d_in[6],
        (const float*)d_in[7],  (const float*)d_in[8],
        (const float*)d_in[9],  (const float*)d_in[10],
        (float*)d_out);
}